// round 4
// baseline (speedup 1.0000x reference)
#include <cuda_runtime.h>
#include <cuda_bf16.h>
#include <mma.h>
#include <cstdint>

using namespace nvcuda;

// Problem constants
#define BB 4
#define SS 2048
#define EE 1024
#define HH 16
#define DD 64
#define MTOT (BB * SS)   // 8192

// ---------------------------------------------------------------------------
// Scratch
// ---------------------------------------------------------------------------
__device__ float g_Q[BB * HH * SS * DD];
__device__ float g_K[BB * HH * SS * DD];
__device__ float g_V[BB * HH * SS * DD];
__device__ float g_O[BB * SS * EE];

__device__ __forceinline__ float to_tf32(float x) {
    uint32_t u;
    asm("cvt.rna.tf32.f32 %0, %1;" : "=r"(u) : "f"(x));
    return __uint_as_float(u);
}

// mma.sync m16n8k8 tf32: D += A(16x8 row) * B(8x8 col)
__device__ __forceinline__ void mma16n8k8(float d[4], const uint32_t a[4],
                                          uint32_t b0, uint32_t b1) {
    asm volatile(
        "mma.sync.aligned.m16n8k8.row.col.f32.tf32.tf32.f32 "
        "{%0,%1,%2,%3}, {%4,%5,%6,%7}, {%8,%9}, {%0,%1,%2,%3};\n"
        : "+f"(d[0]), "+f"(d[1]), "+f"(d[2]), "+f"(d[3])
        : "r"(a[0]), "r"(a[1]), "r"(a[2]), "r"(a[3]), "r"(b0), "r"(b1));
}

// ---------------------------------------------------------------------------
// GEMM + bias:  Y = X[M,K] @ W[K,N] + b
// CTA tile 128x128, BK=32, 256 threads = 8 warps (2 M x 4 N), warp tile 64x32
// (4x2 wmma m16n16k8 tf32). Double-buffered smem + register prefetch.
// MODE 0: Y [M,N]; MODE 1: Y [B,H,S,D] head-split (head = global_col / 64)
// ---------------------------------------------------------------------------
#define GBM 128
#define GBN 128
#define GBK 32
#define GLDA 40    // 32 + 8 pad
#define GLDB 136   // 128 + 8 pad
#define GLDC 132   // 128 + 4 pad

template <int MODE>
__global__ void __launch_bounds__(256) gemm_bias_k(
    const float* __restrict__ X, const float* __restrict__ W,
    const float* __restrict__ bias, float* __restrict__ Y)
{
    extern __shared__ float sm[];
    float* As0 = sm;                        // 128*40 = 5120
    float* As1 = As0 + GBM * GLDA;          // 5120
    float* Bs0 = As1 + GBM * GLDA;          // 32*136 = 4352
    float* Bs1 = Bs0 + GBK * GLDB;          // 4352
    float* Cs  = sm;                        // epilogue reuses A/B area (16896 fits)

    const int tid = threadIdx.x;
    const int wid = tid >> 5;
    const int wm = wid >> 2;                // 0..1  -> M offset wm*64
    const int wn = wid & 3;                 // 0..3  -> N offset wn*32
    const int m0 = blockIdx.y * GBM;
    const int n0 = blockIdx.x * GBN;

    wmma::fragment<wmma::accumulator, 16, 16, 8, float> acc[4][2];
#pragma unroll
    for (int i = 0; i < 4; i++)
#pragma unroll
        for (int j = 0; j < 2; j++) wmma::fill_fragment(acc[i][j], 0.0f);

    // preload stage 0
    {
#pragma unroll
        for (int it = 0; it < 4; it++) {
            int idx = tid + it * 256;
            int r = idx >> 3, cc = (idx & 7) * 4;
            float4 v = *reinterpret_cast<const float4*>(&X[(size_t)(m0 + r) * EE + cc]);
            float* d = &As0[r * GLDA + cc];
            d[0] = to_tf32(v.x); d[1] = to_tf32(v.y);
            d[2] = to_tf32(v.z); d[3] = to_tf32(v.w);
        }
#pragma unroll
        for (int it = 0; it < 4; it++) {
            int idx = tid + it * 256;
            int r = idx >> 5, cc = (idx & 31) * 4;
            float4 v = *reinterpret_cast<const float4*>(&W[(size_t)r * EE + n0 + cc]);
            float* d = &Bs0[r * GLDB + cc];
            d[0] = to_tf32(v.x); d[1] = to_tf32(v.y);
            d[2] = to_tf32(v.z); d[3] = to_tf32(v.w);
        }
    }
    __syncthreads();

    const int NS = EE / GBK;  // 32
    for (int s = 0; s < NS; s++) {
        float* As = (s & 1) ? As1 : As0;
        float* Bs = (s & 1) ? Bs1 : Bs0;
        const bool pf = (s + 1 < NS);
        float4 ra[4], rb[4];
        if (pf) {
            int kb = (s + 1) * GBK;
#pragma unroll
            for (int it = 0; it < 4; it++) {
                int idx = tid + it * 256;
                int r = idx >> 3, cc = (idx & 7) * 4;
                ra[it] = *reinterpret_cast<const float4*>(
                    &X[(size_t)(m0 + r) * EE + kb + cc]);
            }
#pragma unroll
            for (int it = 0; it < 4; it++) {
                int idx = tid + it * 256;
                int r = idx >> 5, cc = (idx & 31) * 4;
                rb[it] = *reinterpret_cast<const float4*>(
                    &W[(size_t)(kb + r) * EE + n0 + cc]);
            }
        }

#pragma unroll
        for (int ks = 0; ks < GBK; ks += 8) {
            wmma::fragment<wmma::matrix_a, 16, 16, 8, wmma::precision::tf32,
                           wmma::row_major> a[4];
            wmma::fragment<wmma::matrix_b, 16, 16, 8, wmma::precision::tf32,
                           wmma::row_major> b[2];
#pragma unroll
            for (int i = 0; i < 4; i++)
                wmma::load_matrix_sync(a[i], &As[(wm * 64 + i * 16) * GLDA + ks], GLDA);
#pragma unroll
            for (int j = 0; j < 2; j++)
                wmma::load_matrix_sync(b[j], &Bs[ks * GLDB + wn * 32 + j * 16], GLDB);
#pragma unroll
            for (int i = 0; i < 4; i++)
#pragma unroll
                for (int j = 0; j < 2; j++)
                    wmma::mma_sync(acc[i][j], a[i], b[j], acc[i][j]);
        }

        if (pf) {
            float* Ad = (s & 1) ? As0 : As1;
            float* Bd = (s & 1) ? Bs0 : Bs1;
#pragma unroll
            for (int it = 0; it < 4; it++) {
                int idx = tid + it * 256;
                int r = idx >> 3, cc = (idx & 7) * 4;
                float* d = &Ad[r * GLDA + cc];
                d[0] = to_tf32(ra[it].x); d[1] = to_tf32(ra[it].y);
                d[2] = to_tf32(ra[it].z); d[3] = to_tf32(ra[it].w);
            }
#pragma unroll
            for (int it = 0; it < 4; it++) {
                int idx = tid + it * 256;
                int r = idx >> 5, cc = (idx & 31) * 4;
                float* d = &Bd[r * GLDB + cc];
                d[0] = to_tf32(rb[it].x); d[1] = to_tf32(rb[it].y);
                d[2] = to_tf32(rb[it].z); d[3] = to_tf32(rb[it].w);
            }
        }
        __syncthreads();
    }

    // epilogue: stage accumulators in smem (reuse A/B buffers), then
    // fused bias + layout-transform store
#pragma unroll
    for (int i = 0; i < 4; i++)
#pragma unroll
        for (int j = 0; j < 2; j++)
            wmma::store_matrix_sync(
                &Cs[(wm * 64 + i * 16) * GLDC + wn * 32 + j * 16],
                acc[i][j], GLDC, wmma::mem_row_major);
    __syncthreads();

#pragma unroll
    for (int it = 0; it < 16; it++) {
        int idx = tid + it * 256;               // 4096 float4 = 128x128
        int r = idx >> 5, cc = (idx & 31) * 4;
        int m = m0 + r;
        float4 v = *reinterpret_cast<const float4*>(&Cs[r * GLDC + cc]);
        float4 bv = *reinterpret_cast<const float4*>(&bias[n0 + cc]);
        v.x += bv.x; v.y += bv.y; v.z += bv.z; v.w += bv.w;
        if (MODE == 0) {
            *reinterpret_cast<float4*>(&Y[(size_t)m * EE + n0 + cc]) = v;
        } else {
            int b = m >> 11;
            int ss = m & 2047;
            int col = n0 + cc;
            int h = col >> 6;
            int d = col & 63;
            *reinterpret_cast<float4*>(
                &Y[(((size_t)(b * HH + h) * SS + ss) * DD) + d]) = v;
        }
    }
}

// ---------------------------------------------------------------------------
// Flash attention: 256 threads, Q-tile 128x64 per CTA, register-resident
// S and O via mma.m16n8k8 tf32. K/V tiles (64 rows) double-buffered in smem.
// (unchanged from R3)
// ---------------------------------------------------------------------------
#define AKLD 68                  // K tile pad
#define AVLD 72                  // V tile pad
#define KBUFF (64 * AKLD)
#define VBUFF (64 * AVLD)
#define ASMEM ((2 * KBUFF + 2 * VBUFF) * 4)   // 71680 bytes

__global__ void __launch_bounds__(256) attn_k(
    const float* __restrict__ Qh, const float* __restrict__ Kh,
    const float* __restrict__ Vh, float* __restrict__ O)
{
    extern __shared__ float sm[];
    float* K0 = sm;
    float* K1 = sm + KBUFF;
    float* V0 = sm + 2 * KBUFF;
    float* V1 = V0 + VBUFF;

    const int tid = threadIdx.x;
    const int lane = tid & 31;
    const int w = tid >> 5;
    const int r = lane >> 2;
    const int c = lane & 3;
    const int qi = blockIdx.x;
    const int bh = blockIdx.y;
    const size_t base = (size_t)bh * SS * DD;
    const int q0 = qi * 128;
    const int rw = q0 + w * 16;

    {
        const float* Qg = Qh + base + (size_t)q0 * DD;
#pragma unroll
        for (int it = 0; it < 8; it++) {
            int g = it * 256 + tid;
            int row = g >> 4, c4 = (g & 15) * 4;
            float4 v = *reinterpret_cast<const float4*>(&Qg[row * DD + c4]);
            float* d = &sm[row * AKLD + c4];
            d[0] = v.x; d[1] = v.y; d[2] = v.z; d[3] = v.w;
        }
    }
    __syncthreads();

    uint32_t Qa[8][4];
    {
        const float scale = 0.125f;
#pragma unroll
        for (int k = 0; k < 8; k++) {
            int kc = k * 8;
            Qa[k][0] = __float_as_uint(to_tf32(sm[(w*16 + r)     * AKLD + kc + c]     * scale));
            Qa[k][1] = __float_as_uint(to_tf32(sm[(w*16 + r + 8) * AKLD + kc + c]     * scale));
            Qa[k][2] = __float_as_uint(to_tf32(sm[(w*16 + r)     * AKLD + kc + c + 4] * scale));
            Qa[k][3] = __float_as_uint(to_tf32(sm[(w*16 + r + 8) * AKLD + kc + c + 4] * scale));
        }
    }
    __syncthreads();

    {
        const float* Kg = Kh + base;
        const float* Vg = Vh + base;
#pragma unroll
        for (int it = 0; it < 4; it++) {
            int g = it * 256 + tid;
            int row = g >> 4, c4 = (g & 15) * 4;
            float4 kv = *reinterpret_cast<const float4*>(&Kg[row * DD + c4]);
            float4 vv = *reinterpret_cast<const float4*>(&Vg[row * DD + c4]);
            float* dk = &K0[row * AKLD + c4];
            dk[0] = to_tf32(kv.x); dk[1] = to_tf32(kv.y);
            dk[2] = to_tf32(kv.z); dk[3] = to_tf32(kv.w);
            float* dv = &V0[row * AVLD + c4];
            dv[0] = to_tf32(vv.x); dv[1] = to_tf32(vv.y);
            dv[2] = to_tf32(vv.z); dv[3] = to_tf32(vv.w);
        }
    }
    __syncthreads();

    float Oa[8][4];
#pragma unroll
    for (int dn = 0; dn < 8; dn++)
#pragma unroll
        for (int e = 0; e < 4; e++) Oa[dn][e] = 0.0f;
    float m0 = -1e30f, m1 = -1e30f, l0 = 0.0f, l1 = 0.0f;

    const int jmax = 2 * qi + 1;
    const int src0 = (lane & ~3) | (c >> 1);
    const int src1 = src0 + 2;
    const bool odd = (c & 1);

    for (int j = 0; j <= jmax; j++) {
        float* Ks = (j & 1) ? K1 : K0;
        float* Vs = (j & 1) ? V1 : V0;
        const bool pf = (j < jmax);
        float4 pk[4], pv[4];
        if (pf) {
            const float* Kg = Kh + base + (size_t)(j + 1) * 64 * DD;
            const float* Vg = Vh + base + (size_t)(j + 1) * 64 * DD;
#pragma unroll
            for (int it = 0; it < 4; it++) {
                int g = it * 256 + tid;
                int row = g >> 4, c4 = (g & 15) * 4;
                pk[it] = *reinterpret_cast<const float4*>(&Kg[row * DD + c4]);
                pv[it] = *reinterpret_cast<const float4*>(&Vg[row * DD + c4]);
            }
        }

        const bool active = (j * 64) <= (rw + 15);
        if (active) {
            float Sa[8][4];
#pragma unroll
            for (int nt = 0; nt < 8; nt++)
#pragma unroll
                for (int e = 0; e < 4; e++) Sa[nt][e] = 0.0f;
#pragma unroll
            for (int k = 0; k < 8; k++) {
#pragma unroll
                for (int nt = 0; nt < 8; nt++) {
                    uint32_t b0 = __float_as_uint(Ks[(nt*8 + r) * AKLD + k*8 + c]);
                    uint32_t b1 = __float_as_uint(Ks[(nt*8 + r) * AKLD + k*8 + c + 4]);
                    mma16n8k8(Sa[nt], Qa[k], b0, b1);
                }
            }

            if (j * 64 + 63 > rw) {
#pragma unroll
                for (int nt = 0; nt < 8; nt++) {
                    int colb = j * 64 + nt * 8 + 2 * c;
                    if (colb     > rw + r)     Sa[nt][0] = -1e30f;
                    if (colb + 1 > rw + r)     Sa[nt][1] = -1e30f;
                    if (colb     > rw + r + 8) Sa[nt][2] = -1e30f;
                    if (colb + 1 > rw + r + 8) Sa[nt][3] = -1e30f;
                }
            }

            float t0 = -1e30f, t1 = -1e30f;
#pragma unroll
            for (int nt = 0; nt < 8; nt++) {
                t0 = fmaxf(t0, fmaxf(Sa[nt][0], Sa[nt][1]));
                t1 = fmaxf(t1, fmaxf(Sa[nt][2], Sa[nt][3]));
            }
            t0 = fmaxf(t0, __shfl_xor_sync(0xffffffffu, t0, 1));
            t0 = fmaxf(t0, __shfl_xor_sync(0xffffffffu, t0, 2));
            t1 = fmaxf(t1, __shfl_xor_sync(0xffffffffu, t1, 1));
            t1 = fmaxf(t1, __shfl_xor_sync(0xffffffffu, t1, 2));
            float mn0 = fmaxf(m0, t0), mn1 = fmaxf(m1, t1);
            float cr0 = __expf(m0 - mn0), cr1 = __expf(m1 - mn1);
            m0 = mn0; m1 = mn1;

            float rs0 = 0.0f, rs1 = 0.0f;
#pragma unroll
            for (int nt = 0; nt < 8; nt++) {
                Sa[nt][0] = __expf(Sa[nt][0] - mn0);
                Sa[nt][1] = __expf(Sa[nt][1] - mn0);
                Sa[nt][2] = __expf(Sa[nt][2] - mn1);
                Sa[nt][3] = __expf(Sa[nt][3] - mn1);
                rs0 += Sa[nt][0] + Sa[nt][1];
                rs1 += Sa[nt][2] + Sa[nt][3];
            }
            rs0 += __shfl_xor_sync(0xffffffffu, rs0, 1);
            rs0 += __shfl_xor_sync(0xffffffffu, rs0, 2);
            rs1 += __shfl_xor_sync(0xffffffffu, rs1, 1);
            rs1 += __shfl_xor_sync(0xffffffffu, rs1, 2);
            l0 = l0 * cr0 + rs0;
            l1 = l1 * cr1 + rs1;

#pragma unroll
            for (int dn = 0; dn < 8; dn++) {
                Oa[dn][0] *= cr0; Oa[dn][1] *= cr0;
                Oa[dn][2] *= cr1; Oa[dn][3] *= cr1;
            }

#pragma unroll
            for (int nt = 0; nt < 8; nt++) {
                float p0 = to_tf32(Sa[nt][0]);
                float p1 = to_tf32(Sa[nt][1]);
                float p2 = to_tf32(Sa[nt][2]);
                float p3 = to_tf32(Sa[nt][3]);
                float x0 = __shfl_sync(0xffffffffu, p0, src0);
                float x1 = __shfl_sync(0xffffffffu, p1, src0);
                float y0 = __shfl_sync(0xffffffffu, p0, src1);
                float y1 = __shfl_sync(0xffffffffu, p1, src1);
                float z0 = __shfl_sync(0xffffffffu, p2, src0);
                float z1 = __shfl_sync(0xffffffffu, p3, src0);
                float u0 = __shfl_sync(0xffffffffu, p2, src1);
                float u1 = __shfl_sync(0xffffffffu, p3, src1);
                uint32_t A[4];
                A[0] = __float_as_uint(odd ? x1 : x0);
                A[1] = __float_as_uint(odd ? z1 : z0);
                A[2] = __float_as_uint(odd ? y1 : y0);
                A[3] = __float_as_uint(odd ? u1 : u0);
#pragma unroll
                for (int dn = 0; dn < 8; dn++) {
                    uint32_t b0 = __float_as_uint(Vs[(nt*8 + c)     * AVLD + dn*8 + r]);
                    uint32_t b1 = __float_as_uint(Vs[(nt*8 + c + 4) * AVLD + dn*8 + r]);
                    mma16n8k8(Oa[dn], A, b0, b1);
                }
            }
        }

        if (pf) {
            float* dK = (j & 1) ? K0 : K1;
            float* dV = (j & 1) ? V0 : V1;
#pragma unroll
            for (int it = 0; it < 4; it++) {
                int g = it * 256 + tid;
                int row = g >> 4, c4 = (g & 15) * 4;
                float* dk = &dK[row * AKLD + c4];
                dk[0] = to_tf32(pk[it].x); dk[1] = to_tf32(pk[it].y);
                dk[2] = to_tf32(pk[it].z); dk[3] = to_tf32(pk[it].w);
                float* dv = &dV[row * AVLD + c4];
                dv[0] = to_tf32(pv[it].x); dv[1] = to_tf32(pv[it].y);
                dv[2] = to_tf32(pv[it].z); dv[3] = to_tf32(pv[it].w);
            }
        }
        __syncthreads();
    }

    const float inv0 = 1.0f / l0;
    const float inv1 = 1.0f / l1;
    const int b = bh >> 4, h = bh & 15;
    const int row0 = rw + r, row1 = rw + r + 8;
    float* O0 = O + ((size_t)b * SS + row0) * EE + h * 64;
    float* O1 = O + ((size_t)b * SS + row1) * EE + h * 64;
#pragma unroll
    for (int dn = 0; dn < 8; dn++) {
        int col = dn * 8 + 2 * c;
        float2 v0 = make_float2(Oa[dn][0] * inv0, Oa[dn][1] * inv0);
        float2 v1 = make_float2(Oa[dn][2] * inv1, Oa[dn][3] * inv1);
        *reinterpret_cast<float2*>(&O0[col]) = v0;
        *reinterpret_cast<float2*>(&O1[col]) = v1;
    }
}

// ---------------------------------------------------------------------------
// Launch
// ---------------------------------------------------------------------------
extern "C" void kernel_launch(void* const* d_in, const int* in_sizes, int n_in,
                              void* d_out, int out_size)
{
    const float* q   = (const float*)d_in[0];
    const float* k   = (const float*)d_in[1];
    const float* v   = (const float*)d_in[2];
    const float* w_q = (const float*)d_in[3];
    const float* b_q = (const float*)d_in[4];
    const float* w_k = (const float*)d_in[5];
    const float* b_k = (const float*)d_in[6];
    const float* w_v = (const float*)d_in[7];
    const float* b_v = (const float*)d_in[8];
    const float* w_o = (const float*)d_in[9];
    const float* b_o = (const float*)d_in[10];
    float* out = (float*)d_out;

    const int gemm_smem = (2 * (GBM * GLDA + GBK * GLDB)) * 4;   // 75776
    const int attn_smem = ASMEM;                                  // 71680

    cudaFuncSetAttribute(gemm_bias_k<0>,
                         cudaFuncAttributeMaxDynamicSharedMemorySize, gemm_smem);
    cudaFuncSetAttribute(gemm_bias_k<1>,
                         cudaFuncAttributeMaxDynamicSharedMemorySize, gemm_smem);
    cudaFuncSetAttribute(attn_k,
                         cudaFuncAttributeMaxDynamicSharedMemorySize, attn_smem);

    float* gQ;  cudaGetSymbolAddress((void**)&gQ, g_Q);
    float* gK;  cudaGetSymbolAddress((void**)&gK, g_K);
    float* gV;  cudaGetSymbolAddress((void**)&gV, g_V);
    float* gO;  cudaGetSymbolAddress((void**)&gO, g_O);

    dim3 ggrid(EE / GBN, MTOT / GBM);  // (8, 64)

    gemm_bias_k<1><<<ggrid, 256, gemm_smem>>>(q, w_q, b_q, gQ);
    gemm_bias_k<1><<<ggrid, 256, gemm_smem>>>(k, w_k, b_k, gK);
    gemm_bias_k<1><<<ggrid, 256, gemm_smem>>>(v, w_v, b_v, gV);

    attn_k<<<dim3(SS / 128, BB * HH), 256, attn_smem>>>(gQ, gK, gV, gO);

    gemm_bias_k<0><<<ggrid, 256, gemm_smem>>>(gO, w_o, b_o, out);
}

// round 5
// speedup vs baseline: 1.8756x; 1.8756x over previous
#include <cuda_runtime.h>
#include <cuda_bf16.h>
#include <cstdint>

// Problem constants
#define BB 4
#define SS 2048
#define EE 1024
#define HH 16
#define DD 64
#define MTOT (BB * SS)   // 8192

// ---------------------------------------------------------------------------
// Scratch
// ---------------------------------------------------------------------------
__device__ float g_Q[BB * HH * SS * DD];
__device__ float g_K[BB * HH * SS * DD];
__device__ float g_V[BB * HH * SS * DD];
__device__ float g_O[BB * SS * EE];

__device__ __forceinline__ float to_tf32(float x) {
    uint32_t u;
    asm("cvt.rna.tf32.f32 %0, %1;" : "=r"(u) : "f"(x));
    return __uint_as_float(u);
}

// mma.sync m16n8k8 tf32: D += A(16x8 row) * B(8x8 col)
__device__ __forceinline__ void mma16n8k8(float d[4], const uint32_t a[4],
                                          uint32_t b0, uint32_t b1) {
    asm volatile(
        "mma.sync.aligned.m16n8k8.row.col.f32.tf32.tf32.f32 "
        "{%0,%1,%2,%3}, {%4,%5,%6,%7}, {%8,%9}, {%0,%1,%2,%3};\n"
        : "+f"(d[0]), "+f"(d[1]), "+f"(d[2]), "+f"(d[3])
        : "r"(a[0]), "r"(a[1]), "r"(a[2]), "r"(a[3]), "r"(b0), "r"(b1));
}

// ---------------------------------------------------------------------------
// GEMM + bias (raw mma.m16n8k8 tf32):  Y = X[M,K] @ W[K,N] + b
// CTA 128x64, BK=32, 256 threads = 8 warps (4 M x 2 N), warp tile 32x32
// = 2(M16) x 4(N8) mma fragments. Double-buffered smem + register prefetch.
// Conflict-free pads: GLDA=36 (banks 4r+c), GLDB=72 (banks 8c+r).
// Epilogue: bias + store direct from accumulator fragments (no smem).
// MODE 0: Y [M,N]; MODE 1: Y [B,H,S,D] head-split (h = blockIdx.x, BN==D==64)
// ---------------------------------------------------------------------------
#define GBM 128
#define GBN 64
#define GBK 32
#define GLDA 36    // 32 + 4 pad
#define GLDB 72    // 64 + 8 pad
#define GSM_FLOATS (2 * (GBM * GLDA + GBK * GLDB))   // 13824 floats = 55296 B

template <int MODE>
__global__ void __launch_bounds__(256) gemm_bias_k(
    const float* __restrict__ X, const float* __restrict__ W,
    const float* __restrict__ bias, float* __restrict__ Y)
{
    extern __shared__ float sm[];
    float* As0 = sm;                        // 128*36 = 4608
    float* As1 = As0 + GBM * GLDA;
    float* Bs0 = As1 + GBM * GLDA;          // 32*72 = 2304
    float* Bs1 = Bs0 + GBK * GLDB;

    const int tid = threadIdx.x;
    const int lane = tid & 31;
    const int wid = tid >> 5;
    const int wm = wid >> 1;                // 0..3 -> M offset wm*32
    const int wn = wid & 1;                 // 0..1 -> N offset wn*32
    const int r = lane >> 2;                // 0..7
    const int c = lane & 3;                 // 0..3
    const int m0 = blockIdx.y * GBM;
    const int n0 = blockIdx.x * GBN;

    float acc[2][4][4];
#pragma unroll
    for (int mf = 0; mf < 2; mf++)
#pragma unroll
        for (int nf = 0; nf < 4; nf++)
#pragma unroll
            for (int e = 0; e < 4; e++) acc[mf][nf][e] = 0.0f;

    // ---- preload stage 0
    {
#pragma unroll
        for (int it = 0; it < 4; it++) {                 // A: 128x32 = 1024 f4
            int idx = tid + it * 256;
            int rr = idx >> 3, cc = (idx & 7) * 4;
            float4 v = *reinterpret_cast<const float4*>(&X[(size_t)(m0 + rr) * EE + cc]);
            float* d = &As0[rr * GLDA + cc];
            d[0] = to_tf32(v.x); d[1] = to_tf32(v.y);
            d[2] = to_tf32(v.z); d[3] = to_tf32(v.w);
        }
#pragma unroll
        for (int it = 0; it < 2; it++) {                 // B: 32x64 = 512 f4
            int idx = tid + it * 256;
            int rr = idx >> 4, cc = (idx & 15) * 4;
            float4 v = *reinterpret_cast<const float4*>(&W[(size_t)rr * EE + n0 + cc]);
            float* d = &Bs0[rr * GLDB + cc];
            d[0] = to_tf32(v.x); d[1] = to_tf32(v.y);
            d[2] = to_tf32(v.z); d[3] = to_tf32(v.w);
        }
    }
    __syncthreads();

    const int NS = EE / GBK;  // 32
    for (int s = 0; s < NS; s++) {
        const float* As = (s & 1) ? As1 : As0;
        const float* Bs = (s & 1) ? Bs1 : Bs0;
        const bool pf = (s + 1 < NS);
        float4 ra[4], rb[2];
        if (pf) {
            int kb = (s + 1) * GBK;
#pragma unroll
            for (int it = 0; it < 4; it++) {
                int idx = tid + it * 256;
                int rr = idx >> 3, cc = (idx & 7) * 4;
                ra[it] = *reinterpret_cast<const float4*>(
                    &X[(size_t)(m0 + rr) * EE + kb + cc]);
            }
#pragma unroll
            for (int it = 0; it < 2; it++) {
                int idx = tid + it * 256;
                int rr = idx >> 4, cc = (idx & 15) * 4;
                rb[it] = *reinterpret_cast<const float4*>(
                    &W[(size_t)(kb + rr) * EE + n0 + cc]);
            }
        }

#pragma unroll
        for (int ks = 0; ks < GBK; ks += 8) {
            uint32_t a[2][4];
#pragma unroll
            for (int mf = 0; mf < 2; mf++) {
                const float* Ab = &As[(wm * 32 + mf * 16) * GLDA + ks];
                a[mf][0] = __float_as_uint(Ab[r * GLDA + c]);
                a[mf][1] = __float_as_uint(Ab[(r + 8) * GLDA + c]);
                a[mf][2] = __float_as_uint(Ab[r * GLDA + c + 4]);
                a[mf][3] = __float_as_uint(Ab[(r + 8) * GLDA + c + 4]);
            }
#pragma unroll
            for (int nf = 0; nf < 4; nf++) {
                const float* Bb = &Bs[ks * GLDB + wn * 32 + nf * 8 + r];
                uint32_t b0 = __float_as_uint(Bb[c * GLDB]);
                uint32_t b1 = __float_as_uint(Bb[(c + 4) * GLDB]);
#pragma unroll
                for (int mf = 0; mf < 2; mf++)
                    mma16n8k8(acc[mf][nf], a[mf], b0, b1);
            }
        }

        if (pf) {
            float* Ad = (s & 1) ? As0 : As1;
            float* Bd = (s & 1) ? Bs0 : Bs1;
#pragma unroll
            for (int it = 0; it < 4; it++) {
                int idx = tid + it * 256;
                int rr = idx >> 3, cc = (idx & 7) * 4;
                float* d = &Ad[rr * GLDA + cc];
                d[0] = to_tf32(ra[it].x); d[1] = to_tf32(ra[it].y);
                d[2] = to_tf32(ra[it].z); d[3] = to_tf32(ra[it].w);
            }
#pragma unroll
            for (int it = 0; it < 2; it++) {
                int idx = tid + it * 256;
                int rr = idx >> 4, cc = (idx & 15) * 4;
                float* d = &Bd[rr * GLDB + cc];
                d[0] = to_tf32(rb[it].x); d[1] = to_tf32(rb[it].y);
                d[2] = to_tf32(rb[it].z); d[3] = to_tf32(rb[it].w);
            }
        }
        __syncthreads();
    }

    // ---- epilogue: bias + store straight from fragments (layout known)
#pragma unroll
    for (int mf = 0; mf < 2; mf++) {
        int m_lo = m0 + wm * 32 + mf * 16 + r;
        int m_hi = m_lo + 8;
#pragma unroll
        for (int nf = 0; nf < 4; nf++) {
            int nl = wn * 32 + nf * 8 + 2 * c;          // local col, even
            float2 bv = *reinterpret_cast<const float2*>(&bias[n0 + nl]);
            float2 vlo = make_float2(acc[mf][nf][0] + bv.x, acc[mf][nf][1] + bv.y);
            float2 vhi = make_float2(acc[mf][nf][2] + bv.x, acc[mf][nf][3] + bv.y);
            if (MODE == 0) {
                *reinterpret_cast<float2*>(&Y[(size_t)m_lo * EE + n0 + nl]) = vlo;
                *reinterpret_cast<float2*>(&Y[(size_t)m_hi * EE + n0 + nl]) = vhi;
            } else {
                int h = blockIdx.x;                      // GBN == 64 == D
                int b_lo = m_lo >> 11, s_lo = m_lo & 2047;
                int b_hi = m_hi >> 11, s_hi = m_hi & 2047;
                *reinterpret_cast<float2*>(
                    &Y[(((size_t)(b_lo * HH + h) * SS + s_lo) * DD) + nl]) = vlo;
                *reinterpret_cast<float2*>(
                    &Y[(((size_t)(b_hi * HH + h) * SS + s_hi) * DD) + nl]) = vhi;
            }
        }
    }
}

// ---------------------------------------------------------------------------
// Flash attention (unchanged from R3): 256 threads, Q-tile 128x64,
// register-resident S/O via mma.m16n8k8 tf32, K/V double-buffered in smem.
// ---------------------------------------------------------------------------
#define AKLD 68
#define AVLD 72
#define KBUFF (64 * AKLD)
#define VBUFF (64 * AVLD)
#define ASMEM ((2 * KBUFF + 2 * VBUFF) * 4)   // 71680 bytes

__global__ void __launch_bounds__(256) attn_k(
    const float* __restrict__ Qh, const float* __restrict__ Kh,
    const float* __restrict__ Vh, float* __restrict__ O)
{
    extern __shared__ float sm[];
    float* K0 = sm;
    float* K1 = sm + KBUFF;
    float* V0 = sm + 2 * KBUFF;
    float* V1 = V0 + VBUFF;

    const int tid = threadIdx.x;
    const int lane = tid & 31;
    const int w = tid >> 5;
    const int r = lane >> 2;
    const int c = lane & 3;
    const int qi = blockIdx.x;
    const int bh = blockIdx.y;
    const size_t base = (size_t)bh * SS * DD;
    const int q0 = qi * 128;
    const int rw = q0 + w * 16;

    {
        const float* Qg = Qh + base + (size_t)q0 * DD;
#pragma unroll
        for (int it = 0; it < 8; it++) {
            int g = it * 256 + tid;
            int row = g >> 4, c4 = (g & 15) * 4;
            float4 v = *reinterpret_cast<const float4*>(&Qg[row * DD + c4]);
            float* d = &sm[row * AKLD + c4];
            d[0] = v.x; d[1] = v.y; d[2] = v.z; d[3] = v.w;
        }
    }
    __syncthreads();

    uint32_t Qa[8][4];
    {
        const float scale = 0.125f;
#pragma unroll
        for (int k = 0; k < 8; k++) {
            int kc = k * 8;
            Qa[k][0] = __float_as_uint(to_tf32(sm[(w*16 + r)     * AKLD + kc + c]     * scale));
            Qa[k][1] = __float_as_uint(to_tf32(sm[(w*16 + r + 8) * AKLD + kc + c]     * scale));
            Qa[k][2] = __float_as_uint(to_tf32(sm[(w*16 + r)     * AKLD + kc + c + 4] * scale));
            Qa[k][3] = __float_as_uint(to_tf32(sm[(w*16 + r + 8) * AKLD + kc + c + 4] * scale));
        }
    }
    __syncthreads();

    {
        const float* Kg = Kh + base;
        const float* Vg = Vh + base;
#pragma unroll
        for (int it = 0; it < 4; it++) {
            int g = it * 256 + tid;
            int row = g >> 4, c4 = (g & 15) * 4;
            float4 kv = *reinterpret_cast<const float4*>(&Kg[row * DD + c4]);
            float4 vv = *reinterpret_cast<const float4*>(&Vg[row * DD + c4]);
            float* dk = &K0[row * AKLD + c4];
            dk[0] = to_tf32(kv.x); dk[1] = to_tf32(kv.y);
            dk[2] = to_tf32(kv.z); dk[3] = to_tf32(kv.w);
            float* dv = &V0[row * AVLD + c4];
            dv[0] = to_tf32(vv.x); dv[1] = to_tf32(vv.y);
            dv[2] = to_tf32(vv.z); dv[3] = to_tf32(vv.w);
        }
    }
    __syncthreads();

    float Oa[8][4];
#pragma unroll
    for (int dn = 0; dn < 8; dn++)
#pragma unroll
        for (int e = 0; e < 4; e++) Oa[dn][e] = 0.0f;
    float m0 = -1e30f, m1 = -1e30f, l0 = 0.0f, l1 = 0.0f;

    const int jmax = 2 * qi + 1;
    const int src0 = (lane & ~3) | (c >> 1);
    const int src1 = src0 + 2;
    const bool odd = (c & 1);

    for (int j = 0; j <= jmax; j++) {
        float* Ks = (j & 1) ? K1 : K0;
        float* Vs = (j & 1) ? V1 : V0;
        const bool pf = (j < jmax);
        float4 pk[4], pv[4];
        if (pf) {
            const float* Kg = Kh + base + (size_t)(j + 1) * 64 * DD;
            const float* Vg = Vh + base + (size_t)(j + 1) * 64 * DD;
#pragma unroll
            for (int it = 0; it < 4; it++) {
                int g = it * 256 + tid;
                int row = g >> 4, c4 = (g & 15) * 4;
                pk[it] = *reinterpret_cast<const float4*>(&Kg[row * DD + c4]);
                pv[it] = *reinterpret_cast<const float4*>(&Vg[row * DD + c4]);
            }
        }

        const bool active = (j * 64) <= (rw + 15);
        if (active) {
            float Sa[8][4];
#pragma unroll
            for (int nt = 0; nt < 8; nt++)
#pragma unroll
                for (int e = 0; e < 4; e++) Sa[nt][e] = 0.0f;
#pragma unroll
            for (int k = 0; k < 8; k++) {
#pragma unroll
                for (int nt = 0; nt < 8; nt++) {
                    uint32_t b0 = __float_as_uint(Ks[(nt*8 + r) * AKLD + k*8 + c]);
                    uint32_t b1 = __float_as_uint(Ks[(nt*8 + r) * AKLD + k*8 + c + 4]);
                    mma16n8k8(Sa[nt], Qa[k], b0, b1);
                }
            }

            if (j * 64 + 63 > rw) {
#pragma unroll
                for (int nt = 0; nt < 8; nt++) {
                    int colb = j * 64 + nt * 8 + 2 * c;
                    if (colb     > rw + r)     Sa[nt][0] = -1e30f;
                    if (colb + 1 > rw + r)     Sa[nt][1] = -1e30f;
                    if (colb     > rw + r + 8) Sa[nt][2] = -1e30f;
                    if (colb + 1 > rw + r + 8) Sa[nt][3] = -1e30f;
                }
            }

            float t0 = -1e30f, t1 = -1e30f;
#pragma unroll
            for (int nt = 0; nt < 8; nt++) {
                t0 = fmaxf(t0, fmaxf(Sa[nt][0], Sa[nt][1]));
                t1 = fmaxf(t1, fmaxf(Sa[nt][2], Sa[nt][3]));
            }
            t0 = fmaxf(t0, __shfl_xor_sync(0xffffffffu, t0, 1));
            t0 = fmaxf(t0, __shfl_xor_sync(0xffffffffu, t0, 2));
            t1 = fmaxf(t1, __shfl_xor_sync(0xffffffffu, t1, 1));
            t1 = fmaxf(t1, __shfl_xor_sync(0xffffffffu, t1, 2));
            float mn0 = fmaxf(m0, t0), mn1 = fmaxf(m1, t1);
            float cr0 = __expf(m0 - mn0), cr1 = __expf(m1 - mn1);
            m0 = mn0; m1 = mn1;

            float rs0 = 0.0f, rs1 = 0.0f;
#pragma unroll
            for (int nt = 0; nt < 8; nt++) {
                Sa[nt][0] = __expf(Sa[nt][0] - mn0);
                Sa[nt][1] = __expf(Sa[nt][1] - mn0);
                Sa[nt][2] = __expf(Sa[nt][2] - mn1);
                Sa[nt][3] = __expf(Sa[nt][3] - mn1);
                rs0 += Sa[nt][0] + Sa[nt][1];
                rs1 += Sa[nt][2] + Sa[nt][3];
            }
            rs0 += __shfl_xor_sync(0xffffffffu, rs0, 1);
            rs0 += __shfl_xor_sync(0xffffffffu, rs0, 2);
            rs1 += __shfl_xor_sync(0xffffffffu, rs1, 1);
            rs1 += __shfl_xor_sync(0xffffffffu, rs1, 2);
            l0 = l0 * cr0 + rs0;
            l1 = l1 * cr1 + rs1;

#pragma unroll
            for (int dn = 0; dn < 8; dn++) {
                Oa[dn][0] *= cr0; Oa[dn][1] *= cr0;
                Oa[dn][2] *= cr1; Oa[dn][3] *= cr1;
            }

#pragma unroll
            for (int nt = 0; nt < 8; nt++) {
                float p0 = to_tf32(Sa[nt][0]);
                float p1 = to_tf32(Sa[nt][1]);
                float p2 = to_tf32(Sa[nt][2]);
                float p3 = to_tf32(Sa[nt][3]);
                float x0 = __shfl_sync(0xffffffffu, p0, src0);
                float x1 = __shfl_sync(0xffffffffu, p1, src0);
                float y0 = __shfl_sync(0xffffffffu, p0, src1);
                float y1 = __shfl_sync(0xffffffffu, p1, src1);
                float z0 = __shfl_sync(0xffffffffu, p2, src0);
                float z1 = __shfl_sync(0xffffffffu, p3, src0);
                float u0 = __shfl_sync(0xffffffffu, p2, src1);
                float u1 = __shfl_sync(0xffffffffu, p3, src1);
                uint32_t A[4];
                A[0] = __float_as_uint(odd ? x1 : x0);
                A[1] = __float_as_uint(odd ? z1 : z0);
                A[2] = __float_as_uint(odd ? y1 : y0);
                A[3] = __float_as_uint(odd ? u1 : u0);
#pragma unroll
                for (int dn = 0; dn < 8; dn++) {
                    uint32_t b0 = __float_as_uint(Vs[(nt*8 + c)     * AVLD + dn*8 + r]);
                    uint32_t b1 = __float_as_uint(Vs[(nt*8 + c + 4) * AVLD + dn*8 + r]);
                    mma16n8k8(Oa[dn], A, b0, b1);
                }
            }
        }

        if (pf) {
            float* dK = (j & 1) ? K0 : K1;
            float* dV = (j & 1) ? V0 : V1;
#pragma unroll
            for (int it = 0; it < 4; it++) {
                int g = it * 256 + tid;
                int row = g >> 4, c4 = (g & 15) * 4;
                float* dk = &dK[row * AKLD + c4];
                dk[0] = to_tf32(pk[it].x); dk[1] = to_tf32(pk[it].y);
                dk[2] = to_tf32(pk[it].z); dk[3] = to_tf32(pk[it].w);
                float* dv = &dV[row * AVLD + c4];
                dv[0] = to_tf32(pv[it].x); dv[1] = to_tf32(pv[it].y);
                dv[2] = to_tf32(pv[it].z); dv[3] = to_tf32(pv[it].w);
            }
        }
        __syncthreads();
    }

    const float inv0 = 1.0f / l0;
    const float inv1 = 1.0f / l1;
    const int b = bh >> 4, h = bh & 15;
    const int row0 = rw + r, row1 = rw + r + 8;
    float* O0 = O + ((size_t)b * SS + row0) * EE + h * 64;
    float* O1 = O + ((size_t)b * SS + row1) * EE + h * 64;
#pragma unroll
    for (int dn = 0; dn < 8; dn++) {
        int col = dn * 8 + 2 * c;
        float2 v0 = make_float2(Oa[dn][0] * inv0, Oa[dn][1] * inv0);
        float2 v1 = make_float2(Oa[dn][2] * inv1, Oa[dn][3] * inv1);
        *reinterpret_cast<float2*>(&O0[col]) = v0;
        *reinterpret_cast<float2*>(&O1[col]) = v1;
    }
}

// ---------------------------------------------------------------------------
// Launch
// ---------------------------------------------------------------------------
extern "C" void kernel_launch(void* const* d_in, const int* in_sizes, int n_in,
                              void* d_out, int out_size)
{
    const float* q   = (const float*)d_in[0];
    const float* k   = (const float*)d_in[1];
    const float* v   = (const float*)d_in[2];
    const float* w_q = (const float*)d_in[3];
    const float* b_q = (const float*)d_in[4];
    const float* w_k = (const float*)d_in[5];
    const float* b_k = (const float*)d_in[6];
    const float* w_v = (const float*)d_in[7];
    const float* b_v = (const float*)d_in[8];
    const float* w_o = (const float*)d_in[9];
    const float* b_o = (const float*)d_in[10];
    float* out = (float*)d_out;

    const int gemm_smem = GSM_FLOATS * 4;   // 55296
    const int attn_smem = ASMEM;            // 71680

    cudaFuncSetAttribute(gemm_bias_k<0>,
                         cudaFuncAttributeMaxDynamicSharedMemorySize, gemm_smem);
    cudaFuncSetAttribute(gemm_bias_k<1>,
                         cudaFuncAttributeMaxDynamicSharedMemorySize, gemm_smem);
    cudaFuncSetAttribute(attn_k,
                         cudaFuncAttributeMaxDynamicSharedMemorySize, attn_smem);

    float* gQ;  cudaGetSymbolAddress((void**)&gQ, g_Q);
    float* gK;  cudaGetSymbolAddress((void**)&gK, g_K);
    float* gV;  cudaGetSymbolAddress((void**)&gV, g_V);
    float* gO;  cudaGetSymbolAddress((void**)&gO, g_O);

    dim3 ggrid(EE / GBN, MTOT / GBM);  // (16, 64)

    gemm_bias_k<1><<<ggrid, 256, gemm_smem>>>(q, w_q, b_q, gQ);
    gemm_bias_k<1><<<ggrid, 256, gemm_smem>>>(k, w_k, b_k, gK);
    gemm_bias_k<1><<<ggrid, 256, gemm_smem>>>(v, w_v, b_v, gV);

    attn_k<<<dim3(SS / 128, BB * HH), 256, attn_smem>>>(gQ, gK, gV, gO);

    gemm_bias_k<0><<<ggrid, 256, gemm_smem>>>(gO, w_o, b_o, out);
}